// round 1
// baseline (speedup 1.0000x reference)
#include <cuda_runtime.h>
#include <math.h>

#define NN 100000
#define EE 1600000
#define DD 192
#define TD 576          // 3*D
#define NB 391          // ceil(NN/256)

// ---------------- scratch (static device allocations; no cudaMalloc allowed) ----
__device__ float g_hp  [NN * DD];   // permuted input rows
__device__ float g_ln  [NN * DD];   // LN1 output
__device__ float g_qkv [NN * TD];   // qkv projections
__device__ float g_score[EE * 4];   // per-edge per-head scores
__device__ float g_agg [NN * DD];   // attention aggregate
__device__ float g_hp2 [NN * DD];   // hp + attn_out
__device__ float g_hn  [NN * DD];   // LN2 output
__device__ float g_act [NN * 384];  // gelu(hn@W1+b1)
__device__ int   g_rank[NN];
__device__ int   g_pinv[NN];
__device__ int   g_rowptr[NN + 1];
__device__ int   g_bsum[NB];
__device__ int   g_bpre[NB];
__device__ int   g_total;
__device__ int   g_isByte;

// ---------------- small helpers ----------------
__device__ __forceinline__ float warp_sum(float v) {
#pragma unroll
    for (int o = 16; o > 0; o >>= 1) v += __shfl_xor_sync(0xffffffffu, v, o);
    return v;
}
__device__ __forceinline__ float warp_max(float v) {
#pragma unroll
    for (int o = 16; o > 0; o >>= 1) v = fmaxf(v, __shfl_xor_sync(0xffffffffu, v, o));
    return v;
}
__device__ __forceinline__ int get_mask(const unsigned char* mb, int i) {
    return g_isByte ? (mb[i] != 0) : (reinterpret_cast<const int*>(mb)[i] != 0);
}

// ---------------- mask dtype sniffing ----------------
__global__ void init_flags_k() { g_isByte = 0; }

__global__ void detect_mask_k(const unsigned char* __restrict__ mb) {
    int i = blockIdx.x * blockDim.x + threadIdx.x;
    if (i >= NN) return;
    // If the mask were int32, every byte at position i%4 != 0 would be zero.
    if ((i & 3) != 0 && mb[i] != 0) atomicOr(&g_isByte, 1);
}

// ---------------- stable-partition rank (train nodes first) ----------------
__global__ void count_k(const unsigned char* __restrict__ mask) {
    int i = blockIdx.x * blockDim.x + threadIdx.x;
    int m = (i < NN) ? get_mask(mask, i) : 0;
    int lane = threadIdx.x & 31, wid = threadIdx.x >> 5;
    unsigned bal = __ballot_sync(0xffffffffu, m);
    __shared__ int ws[8];
    if (lane == 0) ws[wid] = __popc(bal);
    __syncthreads();
    if (threadIdx.x == 0) {
        int s = 0;
#pragma unroll
        for (int w = 0; w < 8; w++) s += ws[w];
        g_bsum[blockIdx.x] = s;
    }
}

__global__ void scan_k() {
    __shared__ int s[NB];
    int t = threadIdx.x;
    if (t < NB) s[t] = g_bsum[t];
    __syncthreads();
    if (t == 0) {
        int run = 0;
        for (int b = 0; b < NB; b++) { int c = s[b]; s[b] = run; run += c; }
        g_total = run;
    }
    __syncthreads();
    if (t < NB) g_bpre[t] = s[t];
}

__global__ void rank_k(const unsigned char* __restrict__ mask) {
    int i = blockIdx.x * blockDim.x + threadIdx.x;
    int m = (i < NN) ? get_mask(mask, i) : 0;
    int lane = threadIdx.x & 31, wid = threadIdx.x >> 5;
    unsigned bal = __ballot_sync(0xffffffffu, m);
    int laneExcl = __popc(bal & ((1u << lane) - 1u));
    __shared__ int ws[8], wp[8];
    if (lane == 0) ws[wid] = __popc(bal);
    __syncthreads();
    if (threadIdx.x == 0) {
        int r = 0;
#pragma unroll
        for (int w = 0; w < 8; w++) { wp[w] = r; r += ws[w]; }
    }
    __syncthreads();
    if (i < NN) {
        int trainBefore = g_bpre[blockIdx.x] + wp[wid] + laneExcl;
        int r = m ? trainBefore : (g_total + (i - trainBefore));
        g_rank[i] = r;       // order[i]
        g_pinv[r] = i;       // inv_order[r]
    }
}

// ---------------- permute + LN1 (warp per row) ----------------
__global__ void perm_ln1_k(const float* __restrict__ x,
                           const float* __restrict__ g, const float* __restrict__ b) {
    int gw = (blockIdx.x * blockDim.x + threadIdx.x) >> 5;
    int lane = threadIdx.x & 31;
    if (gw >= NN) return;
    const float* xr = x + (size_t)g_rank[gw] * DD;
    float v[6];
#pragma unroll
    for (int c = 0; c < 6; c++) v[c] = xr[lane + 32 * c];
    float s = v[0] + v[1] + v[2] + v[3] + v[4] + v[5];
    float mean = warp_sum(s) * (1.0f / DD);
    float q = 0.f;
#pragma unroll
    for (int c = 0; c < 6; c++) { float d = v[c] - mean; q += d * d; }
    float var = warp_sum(q) * (1.0f / DD);
    float rs = rsqrtf(var + 1e-5f);
    float* hpR = g_hp + (size_t)gw * DD;
    float* lnR = g_ln + (size_t)gw * DD;
#pragma unroll
    for (int c = 0; c < 6; c++) {
        int idx = lane + 32 * c;
        hpR[idx] = v[c];
        lnR[idx] = (v[c] - mean) * rs * g[idx] + b[idx];
    }
}

// ---------------- unpermute + LN2 (warp per row) ----------------
__global__ void unperm_ln2_k(float* __restrict__ out,
                             const float* __restrict__ g, const float* __restrict__ b) {
    int gw = (blockIdx.x * blockDim.x + threadIdx.x) >> 5;
    int lane = threadIdx.x & 31;
    if (gw >= NN) return;
    const float* xr = g_hp2 + (size_t)g_pinv[gw] * DD;
    float v[6];
#pragma unroll
    for (int c = 0; c < 6; c++) v[c] = xr[lane + 32 * c];
    float s = v[0] + v[1] + v[2] + v[3] + v[4] + v[5];
    float mean = warp_sum(s) * (1.0f / DD);
    float q = 0.f;
#pragma unroll
    for (int c = 0; c < 6; c++) { float d = v[c] - mean; q += d * d; }
    float var = warp_sum(q) * (1.0f / DD);
    float rs = rsqrtf(var + 1e-5f);
    float* oR  = out  + (size_t)gw * DD;   // h2 stored in d_out
    float* hnR = g_hn + (size_t)gw * DD;
#pragma unroll
    for (int c = 0; c < 6; c++) {
        int idx = lane + 32 * c;
        oR[idx]  = v[c];
        hnR[idx] = (v[c] - mean) * rs * g[idx] + b[idx];
    }
}

// ---------------- generic fp32 GEMM: C = A@B + bias (+gelu | +residual) -------
// EPI: 0 = bias only, 1 = bias+gelu(exact), 2 = bias+residual
template <int EPI>
__global__ void __launch_bounds__(256) gemm_k(const float* __restrict__ A,
                                              const float* __restrict__ B,
                                              const float* __restrict__ bias,
                                              const float* __restrict__ R,
                                              float* __restrict__ C,
                                              int M, int Ncol, int K) {
    __shared__ float As[16][68];   // [k][m], padded (272B rows keep float4 align)
    __shared__ float Bs[16][64];   // [k][n]
    int tid = threadIdx.x;
    int tx = tid & 15, ty = tid >> 4;
    int row0 = blockIdx.y * 64, col0 = blockIdx.x * 64;
    int arow = row0 + (tid >> 2);
    int acb  = (tid & 3) * 4;
    int brow = tid >> 4;
    int bcol = col0 + (tid & 15) * 4;
    float acc[4][4] = {};
    for (int k0 = 0; k0 < K; k0 += 16) {
        float4 av = make_float4(0.f, 0.f, 0.f, 0.f);
        if (arow < M) av = *reinterpret_cast<const float4*>(A + (size_t)arow * K + k0 + acb);
        As[acb + 0][tid >> 2] = av.x;
        As[acb + 1][tid >> 2] = av.y;
        As[acb + 2][tid >> 2] = av.z;
        As[acb + 3][tid >> 2] = av.w;
        *reinterpret_cast<float4*>(&Bs[brow][(tid & 15) * 4]) =
            *reinterpret_cast<const float4*>(B + (size_t)(k0 + brow) * Ncol + bcol);
        __syncthreads();
#pragma unroll
        for (int k = 0; k < 16; k++) {
            float4 a4 = *reinterpret_cast<const float4*>(&As[k][ty * 4]);
            float4 b4 = *reinterpret_cast<const float4*>(&Bs[k][tx * 4]);
            float aa[4] = {a4.x, a4.y, a4.z, a4.w};
            float bb[4] = {b4.x, b4.y, b4.z, b4.w};
#pragma unroll
            for (int i = 0; i < 4; i++)
#pragma unroll
                for (int j = 0; j < 4; j++) acc[i][j] += aa[i] * bb[j];
        }
        __syncthreads();
    }
#pragma unroll
    for (int i = 0; i < 4; i++) {
        int r = row0 + ty * 4 + i;
        if (r >= M) continue;
#pragma unroll
        for (int j = 0; j < 4; j++) {
            int c = col0 + tx * 4 + j;
            float v = acc[i][j] + bias[c];
            if (EPI == 1) v = 0.5f * v * (1.0f + erff(v * 0.70710678118654752f));
            if (EPI == 2) v += R[(size_t)r * Ncol + c];
            C[(size_t)r * Ncol + c] = v;
        }
    }
}

// ---------------- edge scores: one thread per (edge, head) --------------------
__global__ void score_k(const int* __restrict__ src, const int* __restrict__ dst) {
    int t = blockIdx.x * blockDim.x + threadIdx.x;
    if (t >= EE * 4) return;
    int e = t >> 2, h = t & 3;
    const float4* qp = reinterpret_cast<const float4*>(g_qkv + (size_t)dst[e] * TD + h * 144);
    const float4* kp = reinterpret_cast<const float4*>(g_qkv + (size_t)src[e] * TD + h * 144 + 48);
    float acc = 0.f;
#pragma unroll
    for (int r = 0; r < 12; r++) {
        float4 a = qp[r], c = kp[r];
        acc += a.x * c.x + a.y * c.y + a.z * c.z + a.w * c.w;
    }
    g_score[t] = acc * 0.14433756729740643f;   // 1/sqrt(48)
}

// ---------------- CSR row pointers from sorted dst ----------------------------
__global__ void rowptr_k(const int* __restrict__ dst) {
    int e = blockIdx.x * blockDim.x + threadIdx.x;
    if (e >= EE) return;
    int d = dst[e];
    int prev = (e == 0) ? -1 : dst[e - 1];
    for (int n = prev + 1; n <= d; n++) g_rowptr[n] = e;
    if (e == EE - 1)
        for (int n = d + 1; n <= NN; n++) g_rowptr[n] = EE;
}

// ---------------- segment softmax + V aggregation: warp per dst node ----------
__global__ void attn_agg_k(const int* __restrict__ src) {
    int gw = (blockIdx.x * blockDim.x + threadIdx.x) >> 5;
    int lane = threadIdx.x & 31;
    if (gw >= NN) return;
    int e0 = g_rowptr[gw], e1 = g_rowptr[gw + 1];
    float m[4], z[4];
#pragma unroll
    for (int h = 0; h < 4; h++) {
        float mx = -3.4e38f;
        for (int e = e0 + lane; e < e1; e += 32) mx = fmaxf(mx, g_score[e * 4 + h]);
        mx = warp_max(mx);
        float s = 0.f;
        for (int e = e0 + lane; e < e1; e += 32) s += expf(g_score[e * 4 + h] - mx);
        s = warp_sum(s);
        m[h] = mx;
        z[h] = (s > 0.f) ? (1.0f / s) : 0.f;
    }
    float a0 = 0, a1 = 0, a2 = 0, a3 = 0, a4 = 0, a5 = 0;
    bool lo = lane < 16;
    for (int e = e0; e < e1; e++) {
        float4 sc = *reinterpret_cast<const float4*>(g_score + (size_t)e * 4);
        float w0 = expf(sc.x - m[0]) * z[0];
        float w1 = expf(sc.y - m[1]) * z[1];
        float w2 = expf(sc.z - m[2]) * z[2];
        float w3 = expf(sc.w - m[3]) * z[3];
        const float* vr = g_qkv + (size_t)src[e] * TD;
        // out element t = lane + 32*j; head h = t/48; v offset = 96 + t + 96*h
        a0 += w0 * vr[96 + lane];
        a1 += (lo ? w0 : w1) * vr[96 + lane + 32 + (lo ? 0 : 96)];
        a2 += w1 * vr[lane + 256];
        a3 += w2 * vr[lane + 384];
        a4 += (lo ? w2 : w3) * vr[96 + lane + 128 + (lo ? 192 : 288)];
        a5 += w3 * vr[lane + 544];
    }
    float* o = g_agg + (size_t)gw * DD;
    o[lane] = a0; o[lane + 32] = a1; o[lane + 64] = a2;
    o[lane + 96] = a3; o[lane + 128] = a4; o[lane + 160] = a5;
}

// ---------------- launch ------------------------------------------------------
extern "C" void kernel_launch(void* const* d_in, const int* in_sizes, int n_in,
                              void* d_out, int out_size) {
    const float*         x    = (const float*)d_in[0];
    const unsigned char* mask = (const unsigned char*)d_in[1];
    const int*           src  = (const int*)d_in[2];
    const int*           dst  = (const int*)d_in[3];
    const float* ln1g = (const float*)d_in[4];
    const float* ln1b = (const float*)d_in[5];
    const float* Wqkv = (const float*)d_in[6];
    const float* bqkv = (const float*)d_in[7];
    const float* Wout = (const float*)d_in[8];
    const float* bout = (const float*)d_in[9];
    const float* ln2g = (const float*)d_in[10];
    const float* ln2b = (const float*)d_in[11];
    const float* W1   = (const float*)d_in[12];
    const float* b1   = (const float*)d_in[13];
    const float* W2   = (const float*)d_in[14];
    const float* b2   = (const float*)d_in[15];
    float* out = (float*)d_out;

    void *p_hp, *p_ln, *p_qkv, *p_agg, *p_hp2, *p_hn, *p_act;
    cudaGetSymbolAddress(&p_hp,  g_hp);
    cudaGetSymbolAddress(&p_ln,  g_ln);
    cudaGetSymbolAddress(&p_qkv, g_qkv);
    cudaGetSymbolAddress(&p_agg, g_agg);
    cudaGetSymbolAddress(&p_hp2, g_hp2);
    cudaGetSymbolAddress(&p_hn,  g_hn);
    cudaGetSymbolAddress(&p_act, g_act);

    const int RB = (NN * 32 + 255) / 256;     // warp-per-row kernels: 12500 blocks

    init_flags_k<<<1, 1>>>();
    detect_mask_k<<<NB, 256>>>(mask);
    count_k<<<NB, 256>>>(mask);
    scan_k<<<1, 512>>>();
    rank_k<<<NB, 256>>>(mask);

    perm_ln1_k<<<RB, 256>>>(x, ln1g, ln1b);

    gemm_k<0><<<dim3(9, 1563), 256>>>((const float*)p_ln, Wqkv, bqkv, nullptr,
                                      (float*)p_qkv, NN, TD, DD);

    score_k<<<(EE * 4 + 255) / 256, 256>>>(src, dst);
    rowptr_k<<<(EE + 255) / 256, 256>>>(dst);
    attn_agg_k<<<RB, 256>>>(src);

    gemm_k<2><<<dim3(3, 1563), 256>>>((const float*)p_agg, Wout, bout,
                                      (const float*)p_hp, (float*)p_hp2, NN, DD, DD);

    unperm_ln2_k<<<RB, 256>>>(out, ln2g, ln2b);

    gemm_k<1><<<dim3(6, 1563), 256>>>((const float*)p_hn, W1, b1, nullptr,
                                      (float*)p_act, NN, 384, DD);

    gemm_k<2><<<dim3(3, 1563), 256>>>((const float*)p_act, W2, b2,
                                      out, out, NN, DD, 384);
}

// round 4
// speedup vs baseline: 1.3233x; 1.3233x over previous
#include <cuda_runtime.h>
#include <cuda_bf16.h>
#include <stdint.h>
#include <math.h>

typedef __nv_bfloat16 bf16;

#define NN 100000
#define EE 1600000
#define DD 192
#define TD 576
#define NB 391
#define MT 128
#define GRIDM ((NN + MT - 1) / MT)

// ---------------- static scratch ----------------
__device__ float g_hp  [NN * DD];
__device__ float g_qkv [NN * TD];
__device__ float g_score[EE * 4];
__device__ float g_hp2 [NN * DD];
__device__ bf16  g_Ah[NN * DD],  g_Al[NN * DD];      // ln1 -> agg -> ln2 (reused)
__device__ bf16  g_acth[NN * 384], g_actl[NN * 384]; // gelu output
__device__ bf16  g_wqh[TD * DD],  g_wql[TD * DD];    // Wqkv^T  [N][K]
__device__ bf16  g_woh[DD * DD],  g_wol[DD * DD];    // Wout^T
__device__ bf16  g_w1h[384 * DD], g_w1l[384 * DD];   // W1^T
__device__ bf16  g_w2h[DD * 384], g_w2l[DD * 384];   // W2^T
__device__ int   g_rank[NN], g_pinv[NN], g_rowptr[NN + 1];
__device__ int   g_bsum[NB], g_bpre[NB], g_total, g_isByte;

// ---------------- PTX helpers (arch-generic only!) ----------------
__device__ __forceinline__ unsigned s2u(const void* p) {
    unsigned a;
    asm("{ .reg .u64 t; cvta.to.shared.u64 t, %1; cvt.u32.u64 %0, t; }" : "=r"(a) : "l"(p));
    return a;
}
__device__ __forceinline__ void ldm_x4(unsigned addr, unsigned* r) {
    asm volatile("ldmatrix.sync.aligned.m8n8.x4.shared.b16 {%0,%1,%2,%3}, [%4];"
                 : "=r"(r[0]), "=r"(r[1]), "=r"(r[2]), "=r"(r[3]) : "r"(addr));
}
__device__ __forceinline__ void mma16816(float* c, const unsigned* a, const unsigned* b) {
    asm volatile("mma.sync.aligned.m16n8k16.row.col.f32.bf16.bf16.f32 "
                 "{%0,%1,%2,%3},{%4,%5,%6,%7},{%8,%9},{%0,%1,%2,%3};"
                 : "+f"(c[0]), "+f"(c[1]), "+f"(c[2]), "+f"(c[3])
                 : "r"(a[0]), "r"(a[1]), "r"(a[2]), "r"(a[3]), "r"(b[0]), "r"(b[1]));
}

// ---------------- misc helpers ----------------
__device__ __forceinline__ float warp_sum(float v) {
#pragma unroll
    for (int o = 16; o > 0; o >>= 1) v += __shfl_xor_sync(0xffffffffu, v, o);
    return v;
}
__device__ __forceinline__ float warp_max(float v) {
#pragma unroll
    for (int o = 16; o > 0; o >>= 1) v = fmaxf(v, __shfl_xor_sync(0xffffffffu, v, o));
    return v;
}
__device__ __forceinline__ int get_mask(const unsigned char* mb, int i) {
    return g_isByte ? (mb[i] != 0) : (reinterpret_cast<const int*>(mb)[i] != 0);
}
__device__ __forceinline__ void bsplit(float v, bf16& h, bf16& l) {
    h = __float2bfloat16(v);
    l = __float2bfloat16(v - __bfloat162float(h));
}
__device__ __forceinline__ unsigned pack2(bf16 a, bf16 b) {
    unsigned short ua = __bfloat16_as_ushort(a);
    unsigned short ub = __bfloat16_as_ushort(b);
    return (unsigned)ua | ((unsigned)ub << 16);
}

// ---------------- mask sniff + rank ----------------
__global__ void init_flags_k() { g_isByte = 0; }
__global__ void detect_mask_k(const unsigned char* __restrict__ mb) {
    int i = blockIdx.x * blockDim.x + threadIdx.x;
    if (i >= NN) return;
    if ((i & 3) != 0 && mb[i] != 0) atomicOr(&g_isByte, 1);
}
__global__ void count_k(const unsigned char* __restrict__ mask) {
    int i = blockIdx.x * blockDim.x + threadIdx.x;
    int m = (i < NN) ? get_mask(mask, i) : 0;
    int lane = threadIdx.x & 31, wid = threadIdx.x >> 5;
    unsigned bal = __ballot_sync(0xffffffffu, m);
    __shared__ int ws[8];
    if (lane == 0) ws[wid] = __popc(bal);
    __syncthreads();
    if (threadIdx.x == 0) {
        int s = 0;
#pragma unroll
        for (int w = 0; w < 8; w++) s += ws[w];
        g_bsum[blockIdx.x] = s;
    }
}
__global__ void scan_k() {
    __shared__ int s[NB];
    int t = threadIdx.x;
    if (t < NB) s[t] = g_bsum[t];
    __syncthreads();
    if (t == 0) {
        int run = 0;
        for (int b = 0; b < NB; b++) { int c = s[b]; s[b] = run; run += c; }
        g_total = run;
    }
    __syncthreads();
    if (t < NB) g_bpre[t] = s[t];
}
__global__ void rank_k(const unsigned char* __restrict__ mask) {
    int i = blockIdx.x * blockDim.x + threadIdx.x;
    int m = (i < NN) ? get_mask(mask, i) : 0;
    int lane = threadIdx.x & 31, wid = threadIdx.x >> 5;
    unsigned bal = __ballot_sync(0xffffffffu, m);
    int laneExcl = __popc(bal & ((1u << lane) - 1u));
    __shared__ int ws[8], wp[8];
    if (lane == 0) ws[wid] = __popc(bal);
    __syncthreads();
    if (threadIdx.x == 0) {
        int r = 0;
#pragma unroll
        for (int w = 0; w < 8; w++) { wp[w] = r; r += ws[w]; }
    }
    __syncthreads();
    if (i < NN) {
        int trainBefore = g_bpre[blockIdx.x] + wp[wid] + laneExcl;
        int r = m ? trainBefore : (g_total + (i - trainBefore));
        g_rank[i] = r;
        g_pinv[r] = i;
    }
}

// ---------------- permute + LN1 ----------------
__global__ void perm_ln1_k(const float* __restrict__ x,
                           const float* __restrict__ g, const float* __restrict__ b) {
    int gw = (blockIdx.x * blockDim.x + threadIdx.x) >> 5;
    int lane = threadIdx.x & 31;
    if (gw >= NN) return;
    const float* xr = x + (size_t)g_rank[gw] * DD;
    float v[6];
#pragma unroll
    for (int c = 0; c < 6; c++) v[c] = xr[lane + 32 * c];
    float mean = warp_sum(v[0] + v[1] + v[2] + v[3] + v[4] + v[5]) * (1.0f / DD);
    float q = 0.f;
#pragma unroll
    for (int c = 0; c < 6; c++) { float d = v[c] - mean; q += d * d; }
    float rs = rsqrtf(warp_sum(q) * (1.0f / DD) + 1e-5f);
    float* hpR = g_hp + (size_t)gw * DD;
    size_t base = (size_t)gw * DD;
#pragma unroll
    for (int c = 0; c < 6; c++) {
        int idx = lane + 32 * c;
        hpR[idx] = v[c];
        float y = (v[c] - mean) * rs * g[idx] + b[idx];
        bf16 h, l; bsplit(y, h, l);
        g_Ah[base + idx] = h; g_Al[base + idx] = l;
    }
}

// ---------------- unpermute + LN2 ----------------
__global__ void unperm_ln2_k(float* __restrict__ out,
                             const float* __restrict__ g, const float* __restrict__ b) {
    int gw = (blockIdx.x * blockDim.x + threadIdx.x) >> 5;
    int lane = threadIdx.x & 31;
    if (gw >= NN) return;
    const float* xr = g_hp2 + (size_t)g_pinv[gw] * DD;
    float v[6];
#pragma unroll
    for (int c = 0; c < 6; c++) v[c] = xr[lane + 32 * c];
    float mean = warp_sum(v[0] + v[1] + v[2] + v[3] + v[4] + v[5]) * (1.0f / DD);
    float q = 0.f;
#pragma unroll
    for (int c = 0; c < 6; c++) { float d = v[c] - mean; q += d * d; }
    float rs = rsqrtf(warp_sum(q) * (1.0f / DD) + 1e-5f);
    float* oR = out + (size_t)gw * DD;
    size_t base = (size_t)gw * DD;
#pragma unroll
    for (int c = 0; c < 6; c++) {
        int idx = lane + 32 * c;
        oR[idx] = v[c];
        float y = (v[c] - mean) * rs * g[idx] + b[idx];
        bf16 h, l; bsplit(y, h, l);
        g_Ah[base + idx] = h; g_Al[base + idx] = l;
    }
}

// ---------------- weight convert: W[K,N] fp32 -> [N,K] hi/lo bf16 -------------
__global__ void wconv_k(const float* __restrict__ W, bf16* __restrict__ oh,
                        bf16* __restrict__ ol, int K, int N) {
    int i = blockIdx.x * blockDim.x + threadIdx.x;
    if (i >= K * N) return;
    int k = i / N, n = i - k * N;
    bf16 h, l; bsplit(W[i], h, l);
    oh[(size_t)n * K + k] = h;
    ol[(size_t)n * K + k] = l;
}

// ---------------- edge scores ----------------
__global__ void score_k(const int* __restrict__ src, const int* __restrict__ dst) {
    int t = blockIdx.x * blockDim.x + threadIdx.x;
    if (t >= EE * 4) return;
    int e = t >> 2, h = t & 3;
    const float4* qp = reinterpret_cast<const float4*>(g_qkv + (size_t)dst[e] * TD + h * 144);
    const float4* kp = reinterpret_cast<const float4*>(g_qkv + (size_t)src[e] * TD + h * 144 + 48);
    float acc = 0.f;
#pragma unroll
    for (int r = 0; r < 12; r++) {
        float4 a = qp[r], c = kp[r];
        acc += a.x * c.x + a.y * c.y + a.z * c.z + a.w * c.w;
    }
    g_score[t] = acc * 0.14433756729740643f;
}

__global__ void rowptr_k(const int* __restrict__ dst) {
    int e = blockIdx.x * blockDim.x + threadIdx.x;
    if (e >= EE) return;
    int d = dst[e];
    int prev = (e == 0) ? -1 : dst[e - 1];
    for (int n = prev + 1; n <= d; n++) g_rowptr[n] = e;
    if (e == EE - 1)
        for (int n = d + 1; n <= NN; n++) g_rowptr[n] = EE;
}

// ---------------- segment softmax + V agg ----------------
__global__ void attn_agg_k(const int* __restrict__ src) {
    int gw = (blockIdx.x * blockDim.x + threadIdx.x) >> 5;
    int lane = threadIdx.x & 31;
    if (gw >= NN) return;
    int e0 = g_rowptr[gw], e1 = g_rowptr[gw + 1];
    float m[4], z[4];
#pragma unroll
    for (int h = 0; h < 4; h++) {
        float mx = -3.4e38f;
        for (int e = e0 + lane; e < e1; e += 32) mx = fmaxf(mx, g_score[e * 4 + h]);
        mx = warp_max(mx);
        float s = 0.f;
        for (int e = e0 + lane; e < e1; e += 32) s += expf(g_score[e * 4 + h] - mx);
        s = warp_sum(s);
        m[h] = mx;
        z[h] = (s > 0.f) ? (1.0f / s) : 0.f;
    }
    float a0 = 0, a1 = 0, a2 = 0, a3 = 0, a4 = 0, a5 = 0;
    bool lo = lane < 16;
    for (int e = e0; e < e1; e++) {
        float4 sc = *reinterpret_cast<const float4*>(g_score + (size_t)e * 4);
        float w0 = expf(sc.x - m[0]) * z[0];
        float w1 = expf(sc.y - m[1]) * z[1];
        float w2 = expf(sc.z - m[2]) * z[2];
        float w3 = expf(sc.w - m[3]) * z[3];
        const float* vr = g_qkv + (size_t)src[e] * TD;
        a0 += w0 * vr[96 + lane];
        a1 += (lo ? w0 : w1) * vr[96 + lane + 32 + (lo ? 0 : 96)];
        a2 += w1 * vr[lane + 256];
        a3 += w2 * vr[lane + 384];
        a4 += (lo ? w2 : w3) * vr[96 + lane + 128 + (lo ? 192 : 288)];
        a5 += w3 * vr[lane + 544];
    }
    size_t base = (size_t)gw * DD;
    bf16 h, l;
    bsplit(a0, h, l); g_Ah[base + lane] = h;        g_Al[base + lane] = l;
    bsplit(a1, h, l); g_Ah[base + lane + 32] = h;   g_Al[base + lane + 32] = l;
    bsplit(a2, h, l); g_Ah[base + lane + 64] = h;   g_Al[base + lane + 64] = l;
    bsplit(a3, h, l); g_Ah[base + lane + 96] = h;   g_Al[base + lane + 96] = l;
    bsplit(a4, h, l); g_Ah[base + lane + 128] = h;  g_Al[base + lane + 128] = l;
    bsplit(a5, h, l); g_Ah[base + lane + 160] = h;  g_Al[base + lane + 160] = l;
}

// ================== HMMA (mma.sync bf16) GEMM ==================
// SMEM pitch: 200 bf16 per row = 400 bytes -> ldmatrix phases conflict-free.
#define PITCH 200
#define PITCHB 400

// 3-pass compute over one K=192 block. acc[2][NI][4]. aBase/bBase point at hi
// buffers for this warp; aLoOff/bLoOff are byte offsets to the lo buffers.
template <int NI>
__device__ __forceinline__ void compute_pass(unsigned aBase, unsigned bBase,
                                             float (&acc)[2][NI][4]) {
#pragma unroll
    for (int ks = 0; ks < 12; ks++) {
        unsigned k2 = ks * 32u;
        unsigned a0[4], a1[4];
        ldm_x4(aBase + k2, a0);
        ldm_x4(aBase + k2 + 16u * PITCHB, a1);
#pragma unroll
        for (int pr = 0; pr < NI / 2; pr++) {
            unsigned t[4];
            ldm_x4(bBase + k2 + pr * 16u * PITCHB, t);
            unsigned b0[2] = {t[0], t[1]}, b1[2] = {t[2], t[3]};
            mma16816(acc[0][2 * pr], a0, b0);
            mma16816(acc[1][2 * pr], a1, b0);
            mma16816(acc[0][2 * pr + 1], a0, b1);
            mma16816(acc[1][2 * pr + 1], a1, b1);
        }
    }
}

template <int EPI, int NI>
__device__ __forceinline__ void epilogue(float (&acc)[2][NI][4], int row0, int wm,
        int col0, int M, int Ntot, int lane,
        const float* __restrict__ bias, const float* __restrict__ R,
        float* __restrict__ C, bf16* __restrict__ Ch, bf16* __restrict__ Cl) {
    int ro = lane >> 2, co = (lane & 3) * 2;
#pragma unroll
    for (int mi = 0; mi < 2; mi++)
#pragma unroll
    for (int half = 0; half < 2; half++) {
        int gr = row0 + wm * 32 + mi * 16 + half * 8 + ro;
        if (gr >= M) continue;
#pragma unroll
        for (int ni = 0; ni < NI; ni++) {
            int gc = col0 + ni * 8 + co;
            float v0 = acc[mi][ni][half * 2 + 0];
            float v1 = acc[mi][ni][half * 2 + 1];
            float2 b2 = *reinterpret_cast<const float2*>(bias + gc);
            v0 += b2.x; v1 += b2.y;
            size_t o = (size_t)gr * Ntot + gc;
            if (EPI == 1) {
                float g0 = 0.5f * v0 * (1.0f + erff(v0 * 0.70710678118654752f));
                float g1 = 0.5f * v1 * (1.0f + erff(v1 * 0.70710678118654752f));
                bf16 h0, l0, h1, l1;
                bsplit(g0, h0, l0); bsplit(g1, h1, l1);
                *reinterpret_cast<unsigned*>(Ch + o) = pack2(h0, h1);
                *reinterpret_cast<unsigned*>(Cl + o) = pack2(l0, l1);
            } else {
                if (EPI == 2) {
                    float2 r2 = *reinterpret_cast<const float2*>(R + o);
                    v0 += r2.x; v1 += r2.y;
                }
                *reinterpret_cast<float2*>(C + o) = make_float2(v0, v1);
            }
        }
    }
}

// KH1 GEMM: K=192. smem: Ah[128][200] | Al | Bh[64][200] | Bl
#define S1_AL (128 * PITCH)          // elem offsets
#define S1_B  (2 * 128 * PITCH)
#define S1_BL (S1_B + 64 * PITCH)
#define S1_SZ ((S1_BL + 64 * PITCH) * 2)     // 153600 bytes

template <int EPI>
__global__ void __launch_bounds__(256) hmma_gemm_k(
        const bf16* __restrict__ Ah, const bf16* __restrict__ Al,
        const bf16* __restrict__ Bh, const bf16* __restrict__ Bl,
        const float* __restrict__ bias, const float* __restrict__ R,
        float* __restrict__ C, bf16* __restrict__ Ch, bf16* __restrict__ Cl,
        int M, int Ntot) {
    extern __shared__ char smem[];
    bf16* sA = (bf16*)smem;
    bf16* sB = sA + S1_B;
    unsigned sb = s2u(smem);
    int tid = threadIdx.x, lane = tid & 31, wid = tid >> 5;
    int wm = wid & 3, wn = wid >> 2;
    int row0 = blockIdx.x * MT;

    for (int i = tid; i < 128 * 24; i += 256) {
        int r = i / 24, c8 = (i - r * 24) * 8;
        int gr = row0 + r;
        uint4 vh = make_uint4(0u, 0u, 0u, 0u), vl = vh;
        if (gr < M) {
            vh = *reinterpret_cast<const uint4*>(Ah + (size_t)gr * DD + c8);
            vl = *reinterpret_cast<const uint4*>(Al + (size_t)gr * DD + c8);
        }
        *reinterpret_cast<uint4*>(sA + r * PITCH + c8) = vh;
        *reinterpret_cast<uint4*>(sA + S1_AL + r * PITCH + c8) = vl;
    }

    unsigned aAddr = sb + (unsigned)(wm * 32 + (lane & 15)) * PITCHB + ((lane >> 4) << 4);
    unsigned bAddr = sb + S1_B * 2u
                   + (unsigned)(wn * 32 + ((lane >> 4) << 3) + (lane & 7)) * PITCHB
                   + (((lane >> 3) & 1) << 4);
    int numN = Ntot >> 6;
    for (int nt = 0; nt < numN; nt++) {
        if (nt) __syncthreads();
        int n0 = nt * 64;
        for (int i = tid; i < 64 * 24; i += 256) {
            int r = i / 24, c8 = (i - r * 24) * 8;
            int gn = n0 + r;
            *reinterpret_cast<uint4*>(sB + r * PITCH + c8) =
                *reinterpret_cast<const uint4*>(Bh + (size_t)gn * DD + c8);
            *reinterpret_cast<uint4*>(sB + 64 * PITCH + r * PITCH + c8) =
                *reinterpret_cast<const uint4*>(Bl + (size_t)gn * DD + c8);
        }
        __syncthreads();
        float acc[2][4][4];
#pragma unroll
        for (int a = 0; a < 2; a++)
#pragma unroll
            for (int b = 0; b < 4; b++)
#pragma unroll
                for (int c = 0; c < 4; c++) acc[a][b][c] = 0.f;
        // p0: Ah*Bh, p1: Ah*Bl, p2: Al*Bh
        compute_pass<4>(aAddr, bAddr, acc);
        compute_pass<4>(aAddr, bAddr + 64u * PITCHB, acc);
        compute_pass<4>(aAddr + (unsigned)S1_AL * 2u, bAddr, acc);
        epilogue<EPI, 4>(acc, row0, wm, n0 + wn * 32, M, Ntot, lane,
                         bias, R, C, Ch, Cl);
    }
}

// KH2 GEMM (W2): K=384, Ntot=192 fixed. smem: A[128][200] | Bh[192][200] | Bl
#define S2_B  (128 * PITCH)
#define S2_BL (S2_B + 192 * PITCH)
#define S2_SZ ((S2_BL + 192 * PITCH) * 2)    // 204800 bytes

__global__ void __launch_bounds__(256) hmma_gemm2_k(
        const bf16* __restrict__ Ah, const bf16* __restrict__ Al,
        const bf16* __restrict__ Bh, const bf16* __restrict__ Bl,
        const float* __restrict__ bias, const float* __restrict__ R,
        float* __restrict__ C, int M) {
    extern __shared__ char smem[];
    bf16* sA = (bf16*)smem;
    bf16* sB = sA + S2_B;
    unsigned sb = s2u(smem);
    int tid = threadIdx.x, lane = tid & 31, wid = tid >> 5;
    int wm = wid & 3, wn = wid >> 2;
    int row0 = blockIdx.x * MT;

    unsigned aAddr = sb + (unsigned)(wm * 32 + (lane & 15)) * PITCHB + ((lane >> 4) << 4);
    unsigned bAddr = sb + (unsigned)S2_B * 2u
                   + (unsigned)(wn * 96 + ((lane >> 4) << 3) + (lane & 7)) * PITCHB
                   + (((lane >> 3) & 1) << 4);

    float acc[2][12][4];
#pragma unroll
    for (int a = 0; a < 2; a++)
#pragma unroll
        for (int b = 0; b < 12; b++)
#pragma unroll
            for (int c = 0; c < 4; c++) acc[a][b][c] = 0.f;

    for (int kh = 0; kh < 2; kh++) {
        if (kh) __syncthreads();
        int kofs = kh * 192;
        for (int i = tid; i < 192 * 24; i += 256) {
            int r = i / 24, c8 = (i - r * 24) * 8;
            *reinterpret_cast<uint4*>(sB + r * PITCH + c8) =
                *reinterpret_cast<const uint4*>(Bh + (size_t)r * 384 + kofs + c8);
            *reinterpret_cast<uint4*>(sB + 192 * PITCH + r * PITCH + c8) =
                *reinterpret_cast<const uint4*>(Bl + (size_t)r * 384 + kofs + c8);
        }
        for (int i = tid; i < 128 * 24; i += 256) {
            int r = i / 24, c8 = (i - r * 24) * 8;
            int gr = row0 + r;
            uint4 v = make_uint4(0u, 0u, 0u, 0u);
            if (gr < M) v = *reinterpret_cast<const uint4*>(Ah + (size_t)gr * 384 + kofs + c8);
            *reinterpret_cast<uint4*>(sA + r * PITCH + c8) = v;
        }
        __syncthreads();
        compute_pass<12>(aAddr, bAddr, acc);                       // Ah*Bh
        compute_pass<12>(aAddr, bAddr + 192u * PITCHB, acc);       // Ah*Bl
        __syncthreads();
        for (int i = tid; i < 128 * 24; i += 256) {
            int r = i / 24, c8 = (i - r * 24) * 8;
            int gr = row0 + r;
            uint4 v = make_uint4(0u, 0u, 0u, 0u);
            if (gr < M) v = *reinterpret_cast<const uint4*>(Al + (size_t)gr * 384 + kofs + c8);
            *reinterpret_cast<uint4*>(sA + r * PITCH + c8) = v;
        }
        __syncthreads();
        compute_pass<12>(aAddr, bAddr, acc);                       // Al*Bh
    }
    epilogue<2, 12>(acc, row0, wm, wn * 96, M, 192, lane,
                    bias, R, C, nullptr, nullptr);
}

// ---------------- launch ------------------------------------------------------
extern "C" void kernel_launch(void* const* d_in, const int* in_sizes, int n_in,
                              void* d_out, int out_size) {
    const float*         x    = (const float*)d_in[0];
    const unsigned char* mask = (const unsigned char*)d_in[1];
    const int*           src  = (const int*)d_in[2];
    const int*           dst  = (const int*)d_in[3];
    const float* ln1g = (const float*)d_in[4];
    const float* ln1b = (const float*)d_in[5];
    const float* Wqkv = (const float*)d_in[6];
    const float* bqkv = (const float*)d_in[7];
    const float* Wout = (const float*)d_in[8];
    const float* bout = (const float*)d_in[9];
    const float* ln2g = (const float*)d_in[10];
    const float* ln2b = (const float*)d_in[11];
    const float* W1   = (const float*)d_in[12];
    const float* b1   = (const float*)d_in[13];
    const float* W2   = (const float*)d_in[14];
    const float* b2   = (const float*)d_in[15];
    float* out = (float*)d_out;

    void *p_hp, *p_qkv, *p_hp2, *p_Ah, *p_Al, *p_acth, *p_actl;
    void *p_wqh, *p_wql, *p_woh, *p_wol, *p_w1h, *p_w1l, *p_w2h, *p_w2l;
    cudaGetSymbolAddress(&p_hp, g_hp);   cudaGetSymbolAddress(&p_qkv, g_qkv);
    cudaGetSymbolAddress(&p_hp2, g_hp2);
    cudaGetSymbolAddress(&p_Ah, g_Ah);   cudaGetSymbolAddress(&p_Al, g_Al);
    cudaGetSymbolAddress(&p_acth, g_acth); cudaGetSymbolAddress(&p_actl, g_actl);
    cudaGetSymbolAddress(&p_wqh, g_wqh); cudaGetSymbolAddress(&p_wql, g_wql);
    cudaGetSymbolAddress(&p_woh, g_woh); cudaGetSymbolAddress(&p_wol, g_wol);
    cudaGetSymbolAddress(&p_w1h, g_w1h); cudaGetSymbolAddress(&p_w1l, g_w1l);
    cudaGetSymbolAddress(&p_w2h, g_w2h); cudaGetSymbolAddress(&p_w2l, g_w2l);

    cudaFuncSetAttribute(hmma_gemm_k<0>, cudaFuncAttributeMaxDynamicSharedMemorySize, S1_SZ);
    cudaFuncSetAttribute(hmma_gemm_k<1>, cudaFuncAttributeMaxDynamicSharedMemorySize, S1_SZ);
    cudaFuncSetAttribute(hmma_gemm_k<2>, cudaFuncAttributeMaxDynamicSharedMemorySize, S1_SZ);
    cudaFuncSetAttribute(hmma_gemm2_k, cudaFuncAttributeMaxDynamicSharedMemorySize, S2_SZ);

    const int RB = (NN * 32 + 255) / 256;

    init_flags_k<<<1, 1>>>();
    detect_mask_k<<<NB, 256>>>(mask);
    count_k<<<NB, 256>>>(mask);
    scan_k<<<1, 512>>>();
    rank_k<<<NB, 256>>>(mask);

    wconv_k<<<(DD * TD + 255) / 256, 256>>>(Wqkv, (bf16*)p_wqh, (bf16*)p_wql, DD, TD);
    wconv_k<<<(DD * DD + 255) / 256, 256>>>(Wout, (bf16*)p_woh, (bf16*)p_wol, DD, DD);
    wconv_k<<<(DD * 384 + 255) / 256, 256>>>(W1, (bf16*)p_w1h, (bf16*)p_w1l, DD, 384);
    wconv_k<<<(384 * DD + 255) / 256, 256>>>(W2, (bf16*)p_w2h, (bf16*)p_w2l, 384, DD);

    perm_ln1_k<<<RB, 256>>>(x, ln1g, ln1b);

    hmma_gemm_k<0><<<GRIDM, 256, S1_SZ>>>((const bf16*)p_Ah, (const bf16*)p_Al,
        (const bf16*)p_wqh, (const bf16*)p_wql, bqkv, nullptr,
        (float*)p_qkv, nullptr, nullptr, NN, TD);

    score_k<<<(EE * 4 + 255) / 256, 256>>>(src, dst);
    rowptr_k<<<(EE + 255) / 256, 256>>>(dst);
    attn_agg_k<<<RB, 256>>>(src);

    hmma_gemm_k<2><<<GRIDM, 256, S1_SZ>>>((const bf16*)p_Ah, (const bf16*)p_Al,
        (const bf16*)p_woh, (const bf16*)p_wol, bout, (const float*)p_hp,
        (float*)p_hp2, nullptr, nullptr, NN, DD);

    unperm_ln2_k<<<RB, 256>>>(out, ln2g, ln2b);

    hmma_gemm_k<1><<<GRIDM, 256, S1_SZ>>>((const bf16*)p_Ah, (const bf16*)p_Al,
        (const bf16*)p_w1h, (const bf16*)p_w1l, b1, nullptr,
        nullptr, (bf16*)p_acth, (bf16*)p_actl, NN, 384);

    hmma_gemm2_k<<<GRIDM, 256, S2_SZ>>>((const bf16*)p_acth, (const bf16*)p_actl,
        (const bf16*)p_w2h, (const bf16*)p_w2l, b2, out, out, NN);
}